// round 1
// baseline (speedup 1.0000x reference)
#include <cuda_runtime.h>

#define B_  4
#define S_  1024
#define E_  512
#define H_  8
#define DK_ 64
#define M_  (B_ * S_)   // 4096

// Scratch (static device arrays; no allocations anywhere)
__device__ float g_q[B_ * H_ * S_ * DK_];
__device__ float g_k[B_ * H_ * S_ * DK_];
__device__ float g_v[B_ * H_ * S_ * DK_];
__device__ float g_x[B_ * S_ * E_];

// ---------------------------------------------------------------------------
// Fused QKV projection: Y = X @ W^T + b, stored head-split [B,H,S,DK].
// blockIdx.z in {0,1,2} selects (query,Wq,bq,g_q) / (key,...) / (value,...).
// Tiling: BM=BN=64, BK=16, 256 threads (16x16), 4x4 micro-tile per thread.
// ---------------------------------------------------------------------------
__global__ __launch_bounds__(256) void qkv_proj_kernel(
    const float* __restrict__ Xq, const float* __restrict__ Xk, const float* __restrict__ Xv,
    const float* __restrict__ Wq, const float* __restrict__ bq,
    const float* __restrict__ Wk, const float* __restrict__ bk,
    const float* __restrict__ Wv, const float* __restrict__ bv)
{
    __shared__ float Xs[64][20];   // [m][k], padded row 20 -> conflict-free f4 stores
    __shared__ float Ws[16][68];   // [k][f], padded row 68 (16B-aligned rows)

    const int z = blockIdx.z;
    const float* X    = (z == 0) ? Xq : (z == 1) ? Xk : Xv;
    const float* W    = (z == 0) ? Wq : (z == 1) ? Wk : Wv;
    const float* bias = (z == 0) ? bq : (z == 1) ? bk : bv;
    float* dst        = (z == 0) ? g_q : (z == 1) ? g_k : g_v;

    const int tid = threadIdx.x;
    const int tx = tid & 15, ty = tid >> 4;
    const int m0 = blockIdx.x * 64;
    const int f0 = blockIdx.y * 64;

    const int lm = tid >> 2;          // 0..63
    const int le = (tid & 3) << 2;    // 0,4,8,12

    float acc[4][4] = {};

    for (int k0 = 0; k0 < E_; k0 += 16) {
        float4 xv4 = *(const float4*)&X[(size_t)(m0 + lm) * E_ + k0 + le];
        *(float4*)&Xs[lm][le] = xv4;
        float4 wv4 = *(const float4*)&W[(size_t)(f0 + lm) * E_ + k0 + le];
        Ws[le + 0][lm] = wv4.x;
        Ws[le + 1][lm] = wv4.y;
        Ws[le + 2][lm] = wv4.z;
        Ws[le + 3][lm] = wv4.w;
        __syncthreads();

        #pragma unroll
        for (int k = 0; k < 16; k++) {
            float xr[4];
            #pragma unroll
            for (int i = 0; i < 4; i++) xr[i] = Xs[ty * 4 + i][k];
            float wr[4];
            *(float4*)wr = *(const float4*)&Ws[k][tx * 4];
            #pragma unroll
            for (int i = 0; i < 4; i++)
                #pragma unroll
                for (int j = 0; j < 4; j++)
                    acc[i][j] += xr[i] * wr[j];
        }
        __syncthreads();
    }

    // Epilogue: add bias, store head-split. f0 is a multiple of 64 => whole
    // block belongs to one head h = f0/64, d = tx*4+j.
    const int h  = f0 >> 6;
    const int d0 = tx * 4;
    float bb[4];
    #pragma unroll
    for (int j = 0; j < 4; j++) bb[j] = bias[f0 + d0 + j];

    #pragma unroll
    for (int i = 0; i < 4; i++) {
        const int m = m0 + ty * 4 + i;
        const int b = m >> 10;
        const int s = m & (S_ - 1);
        float4 o;
        o.x = acc[i][0] + bb[0];
        o.y = acc[i][1] + bb[1];
        o.z = acc[i][2] + bb[2];
        o.w = acc[i][3] + bb[3];
        *(float4*)&dst[(((size_t)(b * H_ + h)) * S_ + s) * DK_ + d0] = o;
    }
}

// ---------------------------------------------------------------------------
// Output projection: Y = g_x @ Wo^T + bo, plain [B*S, E] store into d_out.
// ---------------------------------------------------------------------------
__global__ __launch_bounds__(256) void out_proj_kernel(
    const float* __restrict__ W, const float* __restrict__ bias, float* __restrict__ Y)
{
    __shared__ float Xs[64][20];
    __shared__ float Ws[16][68];

    const int tid = threadIdx.x;
    const int tx = tid & 15, ty = tid >> 4;
    const int m0 = blockIdx.x * 64;
    const int f0 = blockIdx.y * 64;

    const int lm = tid >> 2;
    const int le = (tid & 3) << 2;

    float acc[4][4] = {};

    for (int k0 = 0; k0 < E_; k0 += 16) {
        float4 xv4 = *(const float4*)&g_x[(size_t)(m0 + lm) * E_ + k0 + le];
        *(float4*)&Xs[lm][le] = xv4;
        float4 wv4 = *(const float4*)&W[(size_t)(f0 + lm) * E_ + k0 + le];
        Ws[le + 0][lm] = wv4.x;
        Ws[le + 1][lm] = wv4.y;
        Ws[le + 2][lm] = wv4.z;
        Ws[le + 3][lm] = wv4.w;
        __syncthreads();

        #pragma unroll
        for (int k = 0; k < 16; k++) {
            float xr[4];
            #pragma unroll
            for (int i = 0; i < 4; i++) xr[i] = Xs[ty * 4 + i][k];
            float wr[4];
            *(float4*)wr = *(const float4*)&Ws[k][tx * 4];
            #pragma unroll
            for (int i = 0; i < 4; i++)
                #pragma unroll
                for (int j = 0; j < 4; j++)
                    acc[i][j] += xr[i] * wr[j];
        }
        __syncthreads();
    }

    const int fcol = f0 + tx * 4;
    float bb[4];
    #pragma unroll
    for (int j = 0; j < 4; j++) bb[j] = bias[fcol + j];

    #pragma unroll
    for (int i = 0; i < 4; i++) {
        const int m = m0 + ty * 4 + i;
        float4 o;
        o.x = acc[i][0] + bb[0];
        o.y = acc[i][1] + bb[1];
        o.z = acc[i][2] + bb[2];
        o.w = acc[i][3] + bb[3];
        *(float4*)&Y[(size_t)m * E_ + fcol] = o;
    }
}

// ---------------------------------------------------------------------------
// Fused attention: per (b,h,q-tile of 64), flash-style streaming over 16
// k-tiles of 64.  Bias (1x1 conv stack) + mask + online softmax fused.
// Thread layout 16x16, each thread owns 4 rows x 4 cols.
// ---------------------------------------------------------------------------
#define ATTN_SMEM_FLOATS (64 * 64 + 64 * 72 + 64 * 64 + 64 * 64)
#define ATTN_SMEM_BYTES  (ATTN_SMEM_FLOATS * 4)

__global__ __launch_bounds__(256) void attn_kernel(
    const float* __restrict__ dist, const int* __restrict__ maskp,
    const float* __restrict__ cw1, const float* __restrict__ cb1,
    const float* __restrict__ cw2, const float* __restrict__ cb2)
{
    extern __shared__ float sm[];
    float* Qs = sm;                  // [64 q][64 d]   natural
    float* Ks = Qs + 64 * 64;        // [64 d][72] (kk) transposed, padded
    float* Vs = Ks + 64 * 72;        // [64 kk][64 d]  natural
    float* Ps = Vs + 64 * 64;        // [64 q][64 kk]  natural

    const int tid = threadIdx.x;
    const int tx = tid & 15, ty = tid >> 4;
    const int bh = blockIdx.x;
    const int b = bh >> 3, h = bh & 7;
    const int q0 = blockIdx.y * 64;

    // per-head 1x1-conv bias params
    float w1[8], b1[8], w2[8];
    #pragma unroll
    for (int i = 0; i < 8; i++) {
        w1[i] = cw1[i];
        b1[i] = cb1[i];
        w2[i] = cw2[h * 8 + i];
    }
    const float b2 = cb2[h];

    const float* Qp = g_q + ((size_t)(b * H_ + h)) * S_ * DK_;
    const float* Kp = g_k + ((size_t)(b * H_ + h)) * S_ * DK_;
    const float* Vp = g_v + ((size_t)(b * H_ + h)) * S_ * DK_;

    // load Q tile (natural layout)
    for (int i4 = tid * 4; i4 < 64 * 64; i4 += 1024) {
        const int r = i4 >> 6, c = i4 & 63;
        *(float4*)&Qs[r * 64 + c] = *(const float4*)&Qp[(size_t)(q0 + r) * DK_ + c];
    }

    float m_run[4], l_run[4], Oacc[4][4];
    #pragma unroll
    for (int i = 0; i < 4; i++) {
        m_run[i] = -1e30f;
        l_run[i] = 0.f;
        #pragma unroll
        for (int j = 0; j < 4; j++) Oacc[i][j] = 0.f;
    }

    for (int k0 = 0; k0 < S_; k0 += 64) {
        // load K transposed + V natural
        for (int i4 = tid * 4; i4 < 64 * 64; i4 += 1024) {
            const int r = i4 >> 6, c = i4 & 63;   // r = key row, c = d
            float4 kv = *(const float4*)&Kp[(size_t)(k0 + r) * DK_ + c];
            Ks[(c + 0) * 72 + r] = kv.x;
            Ks[(c + 1) * 72 + r] = kv.y;
            Ks[(c + 2) * 72 + r] = kv.z;
            Ks[(c + 3) * 72 + r] = kv.w;
            *(float4*)&Vs[r * 64 + c] = *(const float4*)&Vp[(size_t)(k0 + r) * DK_ + c];
        }
        __syncthreads();

        // S = Q K^T  (inner over d, rank-4 chunks)
        float Sacc[4][4] = {};
        #pragma unroll 4
        for (int dc = 0; dc < 64; dc += 4) {
            float qf[4][4];
            #pragma unroll
            for (int i = 0; i < 4; i++)
                *(float4*)&qf[i][0] = *(const float4*)&Qs[(ty * 4 + i) * 64 + dc];
            #pragma unroll
            for (int dd = 0; dd < 4; dd++) {
                float kf[4];
                *(float4*)kf = *(const float4*)&Ks[(dc + dd) * 72 + tx * 4];
                #pragma unroll
                for (int i = 0; i < 4; i++)
                    #pragma unroll
                    for (int j = 0; j < 4; j++)
                        Sacc[i][j] += qf[i][dd] * kf[j];
            }
        }

        // epilogue: scale * bias, mask, online softmax
        #pragma unroll
        for (int i = 0; i < 4; i++) {
            const int qi = q0 + ty * 4 + i;
            const size_t rowbase = ((size_t)b * S_ + qi) * S_ + k0 + tx * 4;
            float dv[4];
            *(float4*)dv = *(const float4*)&dist[rowbase];
            int mv[4];
            *(int4*)mv = *(const int4*)&maskp[rowbase];

            float sv[4];
            #pragma unroll
            for (int j = 0; j < 4; j++) {
                const float d = dv[j];
                float biasv = b2;
                #pragma unroll
                for (int hh = 0; hh < 8; hh++)
                    biasv += fmaxf(fmaf(d, w1[hh], b1[hh]), 0.f) * w2[hh];
                const float s = Sacc[i][j] * 0.125f * biasv;
                sv[j] = (mv[j] == 0) ? -1e9f : s;
            }

            float mx = fmaxf(fmaxf(sv[0], sv[1]), fmaxf(sv[2], sv[3]));
            #pragma unroll
            for (int off = 8; off; off >>= 1)
                mx = fmaxf(mx, __shfl_xor_sync(0xffffffffu, mx, off));
            const float mnew = fmaxf(m_run[i], mx);
            const float corr = __expf(m_run[i] - mnew);
            m_run[i] = mnew;

            float pr[4];
            float rs = 0.f;
            #pragma unroll
            for (int j = 0; j < 4; j++) {
                pr[j] = __expf(sv[j] - mnew);
                rs += pr[j];
            }
            #pragma unroll
            for (int off = 8; off; off >>= 1)
                rs += __shfl_xor_sync(0xffffffffu, rs, off);
            l_run[i] = l_run[i] * corr + rs;
            #pragma unroll
            for (int j = 0; j < 4; j++) Oacc[i][j] *= corr;

            *(float4*)&Ps[(ty * 4 + i) * 64 + tx * 4] = *(float4*)pr;
        }
        __syncthreads();

        // O += P @ V  (inner over kk, rank-4 chunks)
        #pragma unroll 4
        for (int kk = 0; kk < 64; kk += 4) {
            float pf[4][4];
            #pragma unroll
            for (int i = 0; i < 4; i++)
                *(float4*)&pf[i][0] = *(const float4*)&Ps[(ty * 4 + i) * 64 + kk];
            #pragma unroll
            for (int kl = 0; kl < 4; kl++) {
                float vf[4];
                *(float4*)vf = *(const float4*)&Vs[(kk + kl) * 64 + tx * 4];
                #pragma unroll
                for (int i = 0; i < 4; i++)
                    #pragma unroll
                    for (int j = 0; j < 4; j++)
                        Oacc[i][j] += pf[i][kl] * vf[j];
            }
        }
        __syncthreads();
    }

    // normalize and write to g_x in [B,S,E] layout (E = h*64 + d)
    #pragma unroll
    for (int i = 0; i < 4; i++) {
        const int qi = q0 + ty * 4 + i;
        const float inv = 1.0f / l_run[i];
        float4 o;
        o.x = Oacc[i][0] * inv;
        o.y = Oacc[i][1] * inv;
        o.z = Oacc[i][2] * inv;
        o.w = Oacc[i][3] * inv;
        *(float4*)&g_x[((size_t)b * S_ + qi) * E_ + h * 64 + tx * 4] = o;
    }
}

// ---------------------------------------------------------------------------
// Launch
// ---------------------------------------------------------------------------
extern "C" void kernel_launch(void* const* d_in, const int* in_sizes, int n_in,
                              void* d_out, int out_size)
{
    (void)in_sizes; (void)n_in; (void)out_size;
    const float* query = (const float*)d_in[0];
    const float* key   = (const float*)d_in[1];
    const float* value = (const float*)d_in[2];
    const float* dist  = (const float*)d_in[3];
    const int*   maskp = (const int*)  d_in[4];
    const float* Wq = (const float*)d_in[5];
    const float* bq = (const float*)d_in[6];
    const float* Wk = (const float*)d_in[7];
    const float* bk = (const float*)d_in[8];
    const float* Wv = (const float*)d_in[9];
    const float* bv = (const float*)d_in[10];
    const float* Wo = (const float*)d_in[11];
    const float* bo = (const float*)d_in[12];
    const float* cw1 = (const float*)d_in[13];
    const float* cb1 = (const float*)d_in[14];
    const float* cw2 = (const float*)d_in[15];
    const float* cb2 = (const float*)d_in[16];
    float* out = (float*)d_out;

    cudaFuncSetAttribute(attn_kernel,
                         cudaFuncAttributeMaxDynamicSharedMemorySize,
                         ATTN_SMEM_BYTES);

    qkv_proj_kernel<<<dim3(M_ / 64, E_ / 64, 3), 256>>>(
        query, key, value, Wq, bq, Wk, bk, Wv, bv);

    attn_kernel<<<dim3(B_ * H_, S_ / 64), 256, ATTN_SMEM_BYTES>>>(
        dist, maskp, cw1, cb1, cw2, cb2);

    out_proj_kernel<<<dim3(M_ / 64, E_ / 64), 256>>>(Wo, bo, out);
}

// round 5
// speedup vs baseline: 2.1213x; 2.1213x over previous
#include <cuda_runtime.h>
#include <cuda_bf16.h>
#include <cstdint>

#define B_  4
#define S_  1024
#define E_  512
#define H_  8
#define DK_ 64
#define M_  (B_ * S_)   // 4096

typedef __nv_bfloat16  bf16;
typedef __nv_bfloat162 bf162;

// ---------------------------------------------------------------------------
// Static scratch (no allocations anywhere)
// ---------------------------------------------------------------------------
// input splits [M,E]
__device__ bf16 i_qh[M_*E_], i_ql[M_*E_], i_kh[M_*E_], i_kl[M_*E_], i_vh[M_*E_], i_vl[M_*E_];
// weight splits [E,E] (row-major [f][e], i.e. N-major K-contig = B operand layout)
__device__ bf16 w_qh[E_*E_], w_ql[E_*E_], w_kh[E_*E_], w_kl[E_*E_];
__device__ bf16 w_vh[E_*E_], w_vl[E_*E_], w_oh[E_*E_], w_ol[E_*E_];
// projected q/k/v, head-split [B,H,S,DK]
__device__ bf16 p_qh[M_*E_], p_ql[M_*E_], p_kh[M_*E_], p_kl[M_*E_], p_vh[M_*E_], p_vl[M_*E_];
// attention output [M,E]
__device__ bf16 x_h[M_*E_], x_l[M_*E_];

// ---------------------------------------------------------------------------
// MMA / ldmatrix helpers (plain PTX, works at compute_103)
// ---------------------------------------------------------------------------
__device__ __forceinline__ uint32_t smem_u32(const void* p) {
    uint32_t a;
    asm("{ .reg .u64 t; cvta.to.shared.u64 t, %1; cvt.u32.u64 %0, t; }" : "=r"(a) : "l"(p));
    return a;
}
__device__ __forceinline__ void ldsm_x4(uint32_t* r, uint32_t a) {
    asm volatile("ldmatrix.sync.aligned.m8n8.x4.shared.b16 {%0,%1,%2,%3}, [%4];"
                 : "=r"(r[0]), "=r"(r[1]), "=r"(r[2]), "=r"(r[3]) : "r"(a));
}
__device__ __forceinline__ void ldsm_x2(uint32_t* r, uint32_t a) {
    asm volatile("ldmatrix.sync.aligned.m8n8.x2.shared.b16 {%0,%1}, [%2];"
                 : "=r"(r[0]), "=r"(r[1]) : "r"(a));
}
__device__ __forceinline__ void ldsm_x2t(uint32_t* r, uint32_t a) {
    asm volatile("ldmatrix.sync.aligned.m8n8.x2.trans.shared.b16 {%0,%1}, [%2];"
                 : "=r"(r[0]), "=r"(r[1]) : "r"(a));
}
__device__ __forceinline__ void mma_bf16(float* d, const uint32_t* a, const uint32_t* b) {
    asm volatile(
        "mma.sync.aligned.m16n8k16.row.col.f32.bf16.bf16.f32 "
        "{%0,%1,%2,%3}, {%4,%5,%6,%7}, {%8,%9}, {%0,%1,%2,%3};"
        : "+f"(d[0]), "+f"(d[1]), "+f"(d[2]), "+f"(d[3])
        : "r"(a[0]), "r"(a[1]), "r"(a[2]), "r"(a[3]), "r"(b[0]), "r"(b[1]));
}
// split fp32 pair -> packed bf16 hi + packed bf16 lo
__device__ __forceinline__ void split2(float v0, float v1, uint32_t& hi, uint32_t& lo) {
    bf16 h0 = __float2bfloat16(v0);
    bf16 h1 = __float2bfloat16(v1);
    bf16 l0 = __float2bfloat16(v0 - __bfloat162float(h0));
    bf16 l1 = __float2bfloat16(v1 - __bfloat162float(h1));
    bf162 ph; ph.x = h0; ph.y = h1;
    bf162 pl; pl.x = l0; pl.y = l1;
    hi = *(uint32_t*)&ph;
    lo = *(uint32_t*)&pl;
}

// ---------------------------------------------------------------------------
// Conversion: fp32 inputs/weights -> bf16 hi/lo
// ---------------------------------------------------------------------------
__global__ __launch_bounds__(256) void conv7_kernel(
    const float* __restrict__ q, const float* __restrict__ k, const float* __restrict__ v,
    const float* __restrict__ Wq, const float* __restrict__ Wk,
    const float* __restrict__ Wv, const float* __restrict__ Wo)
{
    const int z = blockIdx.z;
    const float* src; bf16 *hi, *lo; int n;
    switch (z) {
        case 0: src = q;  hi = i_qh; lo = i_ql; n = M_*E_; break;
        case 1: src = k;  hi = i_kh; lo = i_kl; n = M_*E_; break;
        case 2: src = v;  hi = i_vh; lo = i_vl; n = M_*E_; break;
        case 3: src = Wq; hi = w_qh; lo = w_ql; n = E_*E_; break;
        case 4: src = Wk; hi = w_kh; lo = w_kl; n = E_*E_; break;
        case 5: src = Wv; hi = w_vh; lo = w_vl; n = E_*E_; break;
        default:src = Wo; hi = w_oh; lo = w_ol; n = E_*E_; break;
    }
    const int idx = (blockIdx.x * 256 + threadIdx.x) * 4;
    if (idx >= n) return;
    float4 f = *(const float4*)(src + idx);
    uint32_t h01, l01, h23, l23;
    split2(f.x, f.y, h01, l01);
    split2(f.z, f.w, h23, l23);
    *(uint32_t*)(hi + idx)     = h01;
    *(uint32_t*)(lo + idx)     = l01;
    *(uint32_t*)(hi + idx + 2) = h23;
    *(uint32_t*)(lo + idx + 2) = l23;
}

// ---------------------------------------------------------------------------
// bf16 hi/lo GEMM: C[M,128-tile] = A @ W^T (+bias).  mma.sync m16n8k16.
// CTA 128x128, 256 thr = 8 warps in 4(M)x2(N), warp tile 32x64.
// ---------------------------------------------------------------------------
#define GST 72                      // smem row stride in bf16 (144 B)
#define GEMM_SMEM_BYTES (4 * 128 * GST * 2)

__device__ __forceinline__ void g2s_128x64(bf16* dst, const bf16* __restrict__ src,
                                           int r0, int k0, int tid) {
    #pragma unroll
    for (int i = 0; i < 4; i++) {
        const int it = tid + i * 256;           // 0..1023
        const int r = it >> 3, c = (it & 7) * 8;
        *(uint4*)&dst[r * GST + c] = *(const uint4*)&src[(size_t)(r0 + r) * E_ + k0 + c];
    }
}

template <int MODE>  // 0: head-split bf16 hi/lo store; 1: flat fp32 store
__device__ __forceinline__ void gemm_body(
    const bf16* __restrict__ Ah, const bf16* __restrict__ Al,
    const bf16* __restrict__ Bh, const bf16* __restrict__ Bl,
    const float* __restrict__ bias, bf16* dh, bf16* dl, float* dout)
{
    extern __shared__ char smem_raw[];
    bf16* sAh = (bf16*)smem_raw;
    bf16* sAl = sAh + 128 * GST;
    bf16* sBh = sAl + 128 * GST;
    bf16* sBl = sBh + 128 * GST;

    const int tid = threadIdx.x, lane = tid & 31, wid = tid >> 5;
    const int wm = wid >> 1, wn = wid & 1;
    const int m0 = blockIdx.x * 128, f0 = blockIdx.y * 128;
    const int l15 = lane & 15;

    float acc[2][8][4] = {};

    for (int k0 = 0; k0 < E_; k0 += 64) {
        if (k0) __syncthreads();
        g2s_128x64(sAh, Ah, m0, k0, tid);
        g2s_128x64(sAl, Al, m0, k0, tid);
        g2s_128x64(sBh, Bh, f0, k0, tid);
        g2s_128x64(sBl, Bl, f0, k0, tid);
        __syncthreads();

        #pragma unroll
        for (int kk = 0; kk < 4; kk++) {
            uint32_t ah[2][4], al[2][4];
            #pragma unroll
            for (int mi = 0; mi < 2; mi++) {
                const int row = wm * 32 + mi * 16 + l15;
                const int col = kk * 16 + (lane >> 4) * 8;
                ldsm_x4(ah[mi], smem_u32(&sAh[row * GST + col]));
                ldsm_x4(al[mi], smem_u32(&sAl[row * GST + col]));
            }
            #pragma unroll
            for (int j = 0; j < 8; j++) {
                const int brow = wn * 64 + j * 8 + (l15 & 7);
                const int bcol = kk * 16 + ((l15 >> 3) & 1) * 8;
                uint32_t bh[2], bl[2];
                ldsm_x2(bh, smem_u32(&sBh[brow * GST + bcol]));
                ldsm_x2(bl, smem_u32(&sBl[brow * GST + bcol]));
                mma_bf16(acc[0][j], ah[0], bh);
                mma_bf16(acc[1][j], ah[1], bh);
                mma_bf16(acc[0][j], al[0], bh);
                mma_bf16(acc[1][j], al[1], bh);
                mma_bf16(acc[0][j], ah[0], bl);
                mma_bf16(acc[1][j], ah[1], bl);
            }
        }
    }

    const int r = lane >> 2, t = lane & 3;
    #pragma unroll
    for (int mi = 0; mi < 2; mi++) {
        #pragma unroll
        for (int j = 0; j < 8; j++) {
            const int f = f0 + wn * 64 + j * 8 + t * 2;
            const float b0 = bias[f], b1 = bias[f + 1];
            #pragma unroll
            for (int c = 0; c < 2; c++) {
                const int row = m0 + wm * 32 + mi * 16 + r + c * 8;
                const float v0 = acc[mi][j][c * 2]     + b0;
                const float v1 = acc[mi][j][c * 2 + 1] + b1;
                if (MODE == 0) {
                    const int bb = row >> 10, s = row & (S_ - 1);
                    const int h = f >> 6, d = f & 63;
                    const size_t o = (((size_t)(bb * H_ + h)) * S_ + s) * DK_ + d;
                    uint32_t hi, lo;
                    split2(v0, v1, hi, lo);
                    *(uint32_t*)&dh[o] = hi;
                    *(uint32_t*)&dl[o] = lo;
                } else {
                    float2 o2; o2.x = v0; o2.y = v1;
                    *(float2*)&dout[(size_t)row * E_ + f] = o2;
                }
            }
        }
    }
}

__global__ __launch_bounds__(256, 1) void gemm_qkv_kernel(
    const float* __restrict__ bq, const float* __restrict__ bk, const float* __restrict__ bv)
{
    const int z = blockIdx.z;
    const bf16 *Ah, *Al, *Bh, *Bl; const float* bias; bf16 *dh, *dl;
    if (z == 0)      { Ah = i_qh; Al = i_ql; Bh = w_qh; Bl = w_ql; bias = bq; dh = p_qh; dl = p_ql; }
    else if (z == 1) { Ah = i_kh; Al = i_kl; Bh = w_kh; Bl = w_kl; bias = bk; dh = p_kh; dl = p_kl; }
    else             { Ah = i_vh; Al = i_vl; Bh = w_vh; Bl = w_vl; bias = bv; dh = p_vh; dl = p_vl; }
    gemm_body<0>(Ah, Al, Bh, Bl, bias, dh, dl, nullptr);
}

__global__ __launch_bounds__(256, 1) void gemm_out_kernel(
    const float* __restrict__ bo, float* __restrict__ out)
{
    gemm_body<1>(x_h, x_l, w_oh, w_ol, bo, nullptr, nullptr, out);
}

// ---------------------------------------------------------------------------
// Tensor-core flash attention with fused conv-bias + mask + online softmax.
// CTA: one (b,h,q-tile of 128). 8 warps, warp owns 16 q-rows.
// Key loop: tiles of 64.  All matmuls mma.sync bf16 hi/lo (3 products).
// ---------------------------------------------------------------------------
#define AST 72
#define ATTN_SMEM_BYTES ((2 * 128 * AST + 4 * 64 * AST) * 2)

__global__ __launch_bounds__(256, 1) void attn_kernel(
    const float* __restrict__ dist, const int* __restrict__ maskp,
    const float* __restrict__ cw1, const float* __restrict__ cb1,
    const float* __restrict__ cw2, const float* __restrict__ cb2)
{
    extern __shared__ char smem_raw[];
    bf16* sQh = (bf16*)smem_raw;
    bf16* sQl = sQh + 128 * AST;
    bf16* sKh = sQl + 128 * AST;
    bf16* sKl = sKh + 64 * AST;
    bf16* sVh = sKl + 64 * AST;
    bf16* sVl = sVh + 64 * AST;

    const int tid = threadIdx.x, lane = tid & 31, w = tid >> 5;
    const int l15 = lane & 15;
    const int r = lane >> 2, t = lane & 3;
    const int bh_ = blockIdx.x;
    const int b = bh_ >> 3, h = bh_ & 7;
    const int q0 = blockIdx.y * 128;

    float w1[8], b1[8], w2[8];
    #pragma unroll
    for (int i = 0; i < 8; i++) { w1[i] = cw1[i]; b1[i] = cb1[i]; w2[i] = cw2[h * 8 + i]; }
    const float b2 = cb2[h];

    const size_t head_off = ((size_t)(b * H_ + h)) * S_ * DK_;
    const bf16* Qh = p_qh + head_off;  const bf16* Ql = p_ql + head_off;
    const bf16* Kh = p_kh + head_off;  const bf16* Kl = p_kl + head_off;
    const bf16* Vh = p_vh + head_off;  const bf16* Vl = p_vl + head_off;

    // stage Q tile (128 x 64)
    #pragma unroll
    for (int i = 0; i < 4; i++) {
        const int it = tid + i * 256;
        const int rr = it >> 3, cc = (it & 7) * 8;
        *(uint4*)&sQh[rr * AST + cc] = *(const uint4*)&Qh[(size_t)(q0 + rr) * DK_ + cc];
        *(uint4*)&sQl[rr * AST + cc] = *(const uint4*)&Ql[(size_t)(q0 + rr) * DK_ + cc];
    }

    float m_run[2], l_run[2], O[8][4];
    m_run[0] = m_run[1] = -1e30f;
    l_run[0] = l_run[1] = 0.f;
    #pragma unroll
    for (int j = 0; j < 8; j++)
        #pragma unroll
        for (int v = 0; v < 4; v++) O[j][v] = 0.f;

    for (int k0 = 0; k0 < S_; k0 += 64) {
        __syncthreads();
        #pragma unroll
        for (int i = 0; i < 2; i++) {
            const int it = tid + i * 256;               // 0..511
            const int rr = it >> 3, cc = (it & 7) * 8;
            *(uint4*)&sKh[rr * AST + cc] = *(const uint4*)&Kh[(size_t)(k0 + rr) * DK_ + cc];
            *(uint4*)&sKl[rr * AST + cc] = *(const uint4*)&Kl[(size_t)(k0 + rr) * DK_ + cc];
            *(uint4*)&sVh[rr * AST + cc] = *(const uint4*)&Vh[(size_t)(k0 + rr) * DK_ + cc];
            *(uint4*)&sVl[rr * AST + cc] = *(const uint4*)&Vl[(size_t)(k0 + rr) * DK_ + cc];
        }
        __syncthreads();

        // ---- S = Q K^T (128x64 per CTA, 16x64 per warp) ----
        float S[8][4] = {};
        #pragma unroll
        for (int kk = 0; kk < 4; kk++) {
            const int qrow = w * 16 + l15;
            const int qcol = kk * 16 + (lane >> 4) * 8;
            uint32_t ah[4], al[4];
            ldsm_x4(ah, smem_u32(&sQh[qrow * AST + qcol]));
            ldsm_x4(al, smem_u32(&sQl[qrow * AST + qcol]));
            #pragma unroll
            for (int j = 0; j < 8; j++) {
                const int krow = j * 8 + (l15 & 7);
                const int kcol = kk * 16 + ((l15 >> 3) & 1) * 8;
                uint32_t bh[2], bl[2];
                ldsm_x2(bh, smem_u32(&sKh[krow * AST + kcol]));
                ldsm_x2(bl, smem_u32(&sKl[krow * AST + kcol]));
                mma_bf16(S[j], ah, bh);
                mma_bf16(S[j], al, bh);
                mma_bf16(S[j], ah, bl);
            }
        }

        // ---- bias * scale, mask, online softmax ----
        float mx[2];
        mx[0] = mx[1] = -1e30f;
        #pragma unroll
        for (int j = 0; j < 8; j++) {
            #pragma unroll
            for (int c = 0; c < 2; c++) {
                const int qg = q0 + w * 16 + r + c * 8;
                const size_t base = ((size_t)b * S_ + qg) * S_ + k0 + j * 8 + t * 2;
                const float2 dv = *(const float2*)&dist[base];
                const int2   mv = *(const int2*)&maskp[base];

                float bias0 = b2, bias1 = b2;
                #pragma unroll
                for (int hh = 0; hh < 8; hh++) {
                    bias0 += fmaxf(fmaf(dv.x, w1[hh], b1[hh]), 0.f) * w2[hh];
                    bias1 += fmaxf(fmaf(dv.y, w1[hh], b1[hh]), 0.f) * w2[hh];
                }
                float s0 = S[j][c * 2]     * 0.125f * bias0;
                float s1 = S[j][c * 2 + 1] * 0.125f * bias1;
                s0 = (mv.x == 0) ? -1e9f : s0;
                s1 = (mv.y == 0) ? -1e9f : s1;
                S[j][c * 2]     = s0;
                S[j][c * 2 + 1] = s1;
                mx[c] = fmaxf(mx[c], fmaxf(s0, s1));
            }
        }
        #pragma unroll
        for (int c = 0; c < 2; c++) {
            mx[c] = fmaxf(mx[c], __shfl_xor_sync(0xffffffffu, mx[c], 1));
            mx[c] = fmaxf(mx[c], __shfl_xor_sync(0xffffffffu, mx[c], 2));
        }
        float corr[2], rs[2];
        #pragma unroll
        for (int c = 0; c < 2; c++) {
            const float mnew = fmaxf(m_run[c], mx[c]);
            corr[c] = __expf(m_run[c] - mnew);
            m_run[c] = mnew;
            rs[c] = 0.f;
        }
        #pragma unroll
        for (int j = 0; j < 8; j++) {
            #pragma unroll
            for (int c = 0; c < 2; c++) {
                const float p0 = __expf(S[j][c * 2]     - m_run[c]);
                const float p1 = __expf(S[j][c * 2 + 1] - m_run[c]);
                S[j][c * 2]     = p0;
                S[j][c * 2 + 1] = p1;
                rs[c] += p0 + p1;
            }
        }
        #pragma unroll
        for (int c = 0; c < 2; c++) {
            rs[c] += __shfl_xor_sync(0xffffffffu, rs[c], 1);
            rs[c] += __shfl_xor_sync(0xffffffffu, rs[c], 2);
            l_run[c] = l_run[c] * corr[c] + rs[c];
        }
        #pragma unroll
        for (int j = 0; j < 8; j++)
            #pragma unroll
            for (int c = 0; c < 2; c++) {
                O[j][c * 2]     *= corr[c];
                O[j][c * 2 + 1] *= corr[c];
            }

        // ---- pack P fragments (register-domain, A-operand layout) ----
        uint32_t pah[4][4], pal[4][4];
        #pragma unroll
        for (int kp = 0; kp < 4; kp++) {
            split2(S[2 * kp][0],     S[2 * kp][1],     pah[kp][0], pal[kp][0]);
            split2(S[2 * kp][2],     S[2 * kp][3],     pah[kp][1], pal[kp][1]);
            split2(S[2 * kp + 1][0], S[2 * kp + 1][1], pah[kp][2], pal[kp][2]);
            split2(S[2 * kp + 1][2], S[2 * kp + 1][3], pah[kp][3], pal[kp][3]);
        }

        // ---- O += P @ V ----
        #pragma unroll
        for (int kp = 0; kp < 4; kp++) {
            #pragma unroll
            for (int dj = 0; dj < 8; dj++) {
                const uint32_t off = (uint32_t)((kp * 16 + l15) * AST + dj * 8);
                uint32_t bh[2], bl[2];
                ldsm_x2t(bh, smem_u32(&sVh[off]));
                ldsm_x2t(bl, smem_u32(&sVl[off]));
                mma_bf16(O[dj], pah[kp], bh);
                mma_bf16(O[dj], pal[kp], bh);
                mma_bf16(O[dj], pah[kp], bl);
            }
        }
    }

    // ---- normalize + split-store to x_h/x_l ----
    const float inv0 = 1.0f / l_run[0];
    const float inv1 = 1.0f / l_run[1];
    #pragma unroll
    for (int dj = 0; dj < 8; dj++) {
        #pragma unroll
        for (int c = 0; c < 2; c++) {
            const int qg = q0 + w * 16 + r + c * 8;
            const int d = dj * 8 + t * 2;
            const float inv = c ? inv1 : inv0;
            uint32_t hi, lo;
            split2(O[dj][c * 2] * inv, O[dj][c * 2 + 1] * inv, hi, lo);
            const size_t o = ((size_t)b * S_ + qg) * E_ + h * 64 + d;
            *(uint32_t*)&x_h[o] = hi;
            *(uint32_t*)&x_l[o] = lo;
        }
    }
}

// ---------------------------------------------------------------------------
// Launch
// ---------------------------------------------------------------------------
extern "C" void kernel_launch(void* const* d_in, const int* in_sizes, int n_in,
                              void* d_out, int out_size)
{
    (void)in_sizes; (void)n_in; (void)out_size;
    const float* query = (const float*)d_in[0];
    const float* key   = (const float*)d_in[1];
    const float* value = (const float*)d_in[2];
    const float* dist  = (const float*)d_in[3];
    const int*   maskp = (const int*)  d_in[4];
    const float* Wq = (const float*)d_in[5];
    const float* bq = (const float*)d_in[6];
    const float* Wk = (const float*)d_in[7];
    const float* bk = (const float*)d_in[8];
    const float* Wv = (const float*)d_in[9];
    const float* bv = (const float*)d_in[10];
    const float* Wo = (const float*)d_in[11];
    const float* bo = (const float*)d_in[12];
    const float* cw1 = (const float*)d_in[13];
    const float* cb1 = (const float*)d_in[14];
    const float* cw2 = (const float*)d_in[15];
    const float* cb2 = (const float*)d_in[16];
    float* out = (float*)d_out;

    cudaFuncSetAttribute(gemm_qkv_kernel, cudaFuncAttributeMaxDynamicSharedMemorySize, GEMM_SMEM_BYTES);
    cudaFuncSetAttribute(gemm_out_kernel, cudaFuncAttributeMaxDynamicSharedMemorySize, GEMM_SMEM_BYTES);
    cudaFuncSetAttribute(attn_kernel,     cudaFuncAttributeMaxDynamicSharedMemorySize, ATTN_SMEM_BYTES);

    conv7_kernel<<<dim3(2048, 1, 7), 256>>>(query, key, value, Wq, Wk, Wv, Wo);

    gemm_qkv_kernel<<<dim3(M_ / 128, E_ / 128, 3), 256, GEMM_SMEM_BYTES>>>(bq, bk, bv);

    attn_kernel<<<dim3(B_ * H_, S_ / 128), 256, ATTN_SMEM_BYTES>>>(
        dist, maskp, cw1, cb1, cw2, cb2);

    gemm_out_kernel<<<dim3(M_ / 128, E_ / 128), 256, GEMM_SMEM_BYTES>>>(bo, out);
}

// round 8
// speedup vs baseline: 2.5747x; 1.2138x over previous
#include <cuda_runtime.h>
#include <cuda_bf16.h>
#include <cstdint>

#define B_  4
#define S_  1024
#define E_  512
#define H_  8
#define DK_ 64
#define M_  (B_ * S_)   // 4096

typedef __nv_bfloat16  bf16;
typedef __nv_bfloat162 bf162;

// ---------------------------------------------------------------------------
// Static scratch (no allocations anywhere)
// ---------------------------------------------------------------------------
__device__ bf16 i_qh[M_*E_], i_ql[M_*E_], i_kh[M_*E_], i_kl[M_*E_], i_vh[M_*E_], i_vl[M_*E_];
__device__ bf16 w_qh[E_*E_], w_ql[E_*E_], w_kh[E_*E_], w_kl[E_*E_];
__device__ bf16 w_vh[E_*E_], w_vl[E_*E_], w_oh[E_*E_], w_ol[E_*E_];
__device__ bf16 p_qh[M_*E_], p_ql[M_*E_], p_kh[M_*E_], p_kl[M_*E_], p_vh[M_*E_], p_vl[M_*E_];
__device__ bf16 x_h[M_*E_], x_l[M_*E_];

// ---------------------------------------------------------------------------
// PTX helpers (all plain compute_103-safe)
// ---------------------------------------------------------------------------
__device__ __forceinline__ uint32_t smem_u32(const void* p) {
    uint32_t a;
    asm("{ .reg .u64 t; cvta.to.shared.u64 t, %1; cvt.u32.u64 %0, t; }" : "=r"(a) : "l"(p));
    return a;
}
__device__ __forceinline__ void ldsm_x4(uint32_t* r, uint32_t a) {
    asm volatile("ldmatrix.sync.aligned.m8n8.x4.shared.b16 {%0,%1,%2,%3}, [%4];"
                 : "=r"(r[0]), "=r"(r[1]), "=r"(r[2]), "=r"(r[3]) : "r"(a));
}
__device__ __forceinline__ void ldsm_x4t(uint32_t* r, uint32_t a) {
    asm volatile("ldmatrix.sync.aligned.m8n8.x4.trans.shared.b16 {%0,%1,%2,%3}, [%4];"
                 : "=r"(r[0]), "=r"(r[1]), "=r"(r[2]), "=r"(r[3]) : "r"(a));
}
__device__ __forceinline__ void mma_bf16(float* d, const uint32_t* a, const uint32_t* b) {
    asm volatile(
        "mma.sync.aligned.m16n8k16.row.col.f32.bf16.bf16.f32 "
        "{%0,%1,%2,%3}, {%4,%5,%6,%7}, {%8,%9}, {%0,%1,%2,%3};"
        : "+f"(d[0]), "+f"(d[1]), "+f"(d[2]), "+f"(d[3])
        : "r"(a[0]), "r"(a[1]), "r"(a[2]), "r"(a[3]), "r"(b[0]), "r"(b[1]));
}
__device__ __forceinline__ void cpa16(uint32_t saddr, const void* g) {
    asm volatile("cp.async.cg.shared.global [%0], [%1], 16;" :: "r"(saddr), "l"(g));
}
#define CP_COMMIT() asm volatile("cp.async.commit_group;" ::: "memory")
#define CP_WAIT(n)  asm volatile("cp.async.wait_group %0;" :: "n"(n) : "memory")

__device__ __forceinline__ void split2(float v0, float v1, uint32_t& hi, uint32_t& lo) {
    bf16 h0 = __float2bfloat16(v0);
    bf16 h1 = __float2bfloat16(v1);
    bf16 l0 = __float2bfloat16(v0 - __bfloat162float(h0));
    bf16 l1 = __float2bfloat16(v1 - __bfloat162float(h1));
    bf162 ph; ph.x = h0; ph.y = h1;
    bf162 pl; pl.x = l0; pl.y = l1;
    hi = *(uint32_t*)&ph;
    lo = *(uint32_t*)&pl;
}

// ---------------------------------------------------------------------------
// fp32 -> bf16 hi/lo conversion
// ---------------------------------------------------------------------------
__global__ __launch_bounds__(256) void conv7_kernel(
    const float* __restrict__ q, const float* __restrict__ k, const float* __restrict__ v,
    const float* __restrict__ Wq, const float* __restrict__ Wk,
    const float* __restrict__ Wv, const float* __restrict__ Wo)
{
    const int z = blockIdx.z;
    const float* src; bf16 *hi, *lo; int n;
    switch (z) {
        case 0: src = q;  hi = i_qh; lo = i_ql; n = M_*E_; break;
        case 1: src = k;  hi = i_kh; lo = i_kl; n = M_*E_; break;
        case 2: src = v;  hi = i_vh; lo = i_vl; n = M_*E_; break;
        case 3: src = Wq; hi = w_qh; lo = w_ql; n = E_*E_; break;
        case 4: src = Wk; hi = w_kh; lo = w_kl; n = E_*E_; break;
        case 5: src = Wv; hi = w_vh; lo = w_vl; n = E_*E_; break;
        default:src = Wo; hi = w_oh; lo = w_ol; n = E_*E_; break;
    }
    const int idx = (blockIdx.x * 256 + threadIdx.x) * 4;
    if (idx >= n) return;
    float4 f = *(const float4*)(src + idx);
    uint32_t h01, l01, h23, l23;
    split2(f.x, f.y, h01, l01);
    split2(f.z, f.w, h23, l23);
    *(uint32_t*)(hi + idx)     = h01;
    *(uint32_t*)(lo + idx)     = l01;
    *(uint32_t*)(hi + idx + 2) = h23;
    *(uint32_t*)(lo + idx + 2) = l23;
}

// ---------------------------------------------------------------------------
// Pipelined bf16 hi/lo GEMM.  CTA 128x128, warp 32x64, cp.async double buffer.
// ---------------------------------------------------------------------------
#define GST 72
#define GTILE_B (128 * GST * 2)                 // 18432 B / tile
#define GEMM_SMEM_BYTES (2 * 4 * GTILE_B)       // 147456 B

__device__ __forceinline__ void g2s_cp(uint32_t sbase, const bf16* __restrict__ src,
                                       int r0, int k0, int tid) {
    #pragma unroll
    for (int i = 0; i < 4; i++) {
        const int it = tid + i * 256;
        const int r = it >> 3, c = (it & 7) * 8;
        cpa16(sbase + (uint32_t)(r * GST + c) * 2,
              src + (size_t)(r0 + r) * E_ + k0 + c);
    }
}

template <int MODE>  // 0: head-split bf16 hi/lo store; 1: flat fp32 store
__device__ __forceinline__ void gemm_body(
    const bf16* __restrict__ Ah, const bf16* __restrict__ Al,
    const bf16* __restrict__ Bh, const bf16* __restrict__ Bl,
    const float* __restrict__ bias, bf16* dh, bf16* dl, float* dout)
{
    extern __shared__ char smem_raw[];
    const uint32_t sb = smem_u32(smem_raw);

    const int tid = threadIdx.x, lane = tid & 31, wid = tid >> 5;
    const int wm = wid >> 1, wn = wid & 1;
    const int m0 = blockIdx.x * 128, f0 = blockIdx.y * 128;
    const int l15 = lane & 15;
    const int g = lane >> 3;

    float acc[2][8][4] = {};

    // prologue: stage k-chunk 0
    {
        const uint32_t base = sb;
        g2s_cp(base,               Ah, m0, 0, tid);
        g2s_cp(base + GTILE_B,     Al, m0, 0, tid);
        g2s_cp(base + 2 * GTILE_B, Bh, f0, 0, tid);
        g2s_cp(base + 3 * GTILE_B, Bl, f0, 0, tid);
    }
    CP_COMMIT();

    for (int kc = 0; kc < 8; kc++) {
        const int buf = kc & 1;
        if (kc + 1 < 8) {
            const uint32_t base = sb + (uint32_t)(buf ^ 1) * 4 * GTILE_B;
            g2s_cp(base,               Ah, m0, (kc + 1) * 64, tid);
            g2s_cp(base + GTILE_B,     Al, m0, (kc + 1) * 64, tid);
            g2s_cp(base + 2 * GTILE_B, Bh, f0, (kc + 1) * 64, tid);
            g2s_cp(base + 3 * GTILE_B, Bl, f0, (kc + 1) * 64, tid);
        }
        CP_COMMIT();
        CP_WAIT(1);
        __syncthreads();

        const uint32_t sAh = sb + (uint32_t)buf * 4 * GTILE_B;
        const uint32_t sAl = sAh + GTILE_B;
        const uint32_t sBh = sAh + 2 * GTILE_B;
        const uint32_t sBl = sAh + 3 * GTILE_B;

        #pragma unroll
        for (int kk = 0; kk < 4; kk++) {
            const int acol = kk * 16 + (lane >> 4) * 8;
            uint32_t ah[2][4], al[2][4];
            #pragma unroll
            for (int mi = 0; mi < 2; mi++) {
                const uint32_t ao = (uint32_t)((wm * 32 + mi * 16 + l15) * GST + acol) * 2;
                ldsm_x4(ah[mi], sAh + ao);
                ldsm_x4(al[mi], sAl + ao);
            }
            uint32_t bh[4][4], bl[4][4];
            #pragma unroll
            for (int jj = 0; jj < 4; jj++) {
                const uint32_t bo = (uint32_t)((wn * 64 + jj * 16 + (g >> 1) * 8 + (lane & 7)) * GST
                                               + kk * 16 + (g & 1) * 8) * 2;
                ldsm_x4(bh[jj], sBh + bo);
                ldsm_x4(bl[jj], sBl + bo);
            }
            #pragma unroll
            for (int jj = 0; jj < 4; jj++) {
                #pragma unroll
                for (int half = 0; half < 2; half++) {
                    const int j = jj * 2 + half;
                    const uint32_t* Bh2 = &bh[jj][half * 2];
                    const uint32_t* Bl2 = &bl[jj][half * 2];
                    mma_bf16(acc[0][j], ah[0], Bh2);
                    mma_bf16(acc[1][j], ah[1], Bh2);
                    mma_bf16(acc[0][j], al[0], Bh2);
                    mma_bf16(acc[1][j], al[1], Bh2);
                    mma_bf16(acc[0][j], ah[0], Bl2);
                    mma_bf16(acc[1][j], ah[1], Bl2);
                }
            }
        }
        __syncthreads();
    }

    const int r = lane >> 2, t = lane & 3;
    #pragma unroll
    for (int mi = 0; mi < 2; mi++) {
        #pragma unroll
        for (int j = 0; j < 8; j++) {
            const int f = f0 + wn * 64 + j * 8 + t * 2;
            const float b0 = bias[f], b1 = bias[f + 1];
            #pragma unroll
            for (int c = 0; c < 2; c++) {
                const int row = m0 + wm * 32 + mi * 16 + r + c * 8;
                const float v0 = acc[mi][j][c * 2]     + b0;
                const float v1 = acc[mi][j][c * 2 + 1] + b1;
                if (MODE == 0) {
                    const int bb = row >> 10, s = row & (S_ - 1);
                    const int h = f >> 6, d = f & 63;
                    const size_t o = (((size_t)(bb * H_ + h)) * S_ + s) * DK_ + d;
                    uint32_t hi, lo;
                    split2(v0, v1, hi, lo);
                    *(uint32_t*)&dh[o] = hi;
                    *(uint32_t*)&dl[o] = lo;
                } else {
                    float2 o2; o2.x = v0; o2.y = v1;
                    *(float2*)&dout[(size_t)row * E_ + f] = o2;
                }
            }
        }
    }
}

__global__ __launch_bounds__(256, 1) void gemm_qkv_kernel(
    const float* __restrict__ bq, const float* __restrict__ bk, const float* __restrict__ bv)
{
    const int z = blockIdx.z;
    const bf16 *Ah, *Al, *Bh, *Bl; const float* bias; bf16 *dh, *dl;
    if (z == 0)      { Ah = i_qh; Al = i_ql; Bh = w_qh; Bl = w_ql; bias = bq; dh = p_qh; dl = p_ql; }
    else if (z == 1) { Ah = i_kh; Al = i_kl; Bh = w_kh; Bl = w_kl; bias = bk; dh = p_kh; dl = p_kl; }
    else             { Ah = i_vh; Al = i_vl; Bh = w_vh; Bl = w_vl; bias = bv; dh = p_vh; dl = p_vl; }
    gemm_body<0>(Ah, Al, Bh, Bl, bias, dh, dl, nullptr);
}

__global__ __launch_bounds__(256, 1) void gemm_out_kernel(
    const float* __restrict__ bo, float* __restrict__ out)
{
    gemm_body<1>(x_h, x_l, w_oh, w_ol, bo, nullptr, nullptr, out);
}

// ---------------------------------------------------------------------------
// Pipelined tensor-core flash attention with fused conv-bias/mask/softmax.
// CTA = (b,h,128-q-tile), 8 warps (16 q-rows each), k-tiles of 64.
// cp.async: K/V double-buffered, dist/mask staged per tile.
// ---------------------------------------------------------------------------
#define AST 72
#define KV_TILE_B (64 * AST * 2)                 // 9216 B per array
#define KV_BUF_B  (4 * KV_TILE_B)                // 36864 B per buffer
#define DMST 68
#define SQ_BYTES   (2 * 128 * AST * 2)           // 36864
#define DM_BYTES   (128 * DMST * 4)              // 34816
#define ATTN_SMEM_BYTES (SQ_BYTES + 2 * KV_BUF_B + 2 * DM_BYTES)  // 180224

__global__ __launch_bounds__(256, 1) void attn_kernel(
    const float* __restrict__ dist, const int* __restrict__ maskp,
    const float* __restrict__ cw1, const float* __restrict__ cb1,
    const float* __restrict__ cw2, const float* __restrict__ cb2)
{
    extern __shared__ char smem_raw[];
    const uint32_t sb   = smem_u32(smem_raw);
    const uint32_t sQh  = sb;
    const uint32_t sQl  = sb + 128 * AST * 2;
    const uint32_t sKV0 = sb + SQ_BYTES;                 // 2 buffers follow
    const uint32_t sDist = sb + SQ_BYTES + 2 * KV_BUF_B;
    const uint32_t sMask = sDist + DM_BYTES;
    float* fDist = (float*)(smem_raw + SQ_BYTES + 2 * KV_BUF_B);
    int*   iMask = (int*)(smem_raw + SQ_BYTES + 2 * KV_BUF_B + DM_BYTES);

    const int tid = threadIdx.x, lane = tid & 31, w = tid >> 5;
    const int l15 = lane & 15;
    const int g = lane >> 3;
    const int r = lane >> 2, t = lane & 3;
    const int bh_ = blockIdx.x;
    const int b = bh_ >> 3, h = bh_ & 7;
    const int q0 = blockIdx.y * 128;

    float w1[8], b1[8], w2[8];
    #pragma unroll
    for (int i = 0; i < 8; i++) { w1[i] = cw1[i]; b1[i] = cb1[i]; w2[i] = cw2[h * 8 + i]; }
    const float b2 = cb2[h];

    const size_t head_off = ((size_t)(b * H_ + h)) * S_ * DK_;
    const bf16* Qh = p_qh + head_off;  const bf16* Ql = p_ql + head_off;
    const bf16* Kh = p_kh + head_off;  const bf16* Kl = p_kl + head_off;
    const bf16* Vh = p_vh + head_off;  const bf16* Vl = p_vl + head_off;

    // stage Q (cp.async, folded into group 0)
    #pragma unroll
    for (int i = 0; i < 4; i++) {
        const int it = tid + i * 256;
        const int rr = it >> 3, cc = (it & 7) * 8;
        cpa16(sQh + (uint32_t)(rr * AST + cc) * 2, Qh + (size_t)(q0 + rr) * DK_ + cc);
        cpa16(sQl + (uint32_t)(rr * AST + cc) * 2, Ql + (size_t)(q0 + rr) * DK_ + cc);
    }
    // stage KV tile 0 into buffer 0
    #pragma unroll
    for (int i = 0; i < 2; i++) {
        const int it = tid + i * 256;
        const int rr = it >> 3, cc = (it & 7) * 8;
        const uint32_t so = (uint32_t)(rr * AST + cc) * 2;
        const size_t go = (size_t)rr * DK_ + cc;
        cpa16(sKV0 + so,                 Kh + go);
        cpa16(sKV0 + KV_TILE_B + so,     Kl + go);
        cpa16(sKV0 + 2 * KV_TILE_B + so, Vh + go);
        cpa16(sKV0 + 3 * KV_TILE_B + so, Vl + go);
    }
    CP_COMMIT();

    float m_run[2], l_run[2], O[8][4];
    m_run[0] = m_run[1] = -1e30f;
    l_run[0] = l_run[1] = 0.f;
    #pragma unroll
    for (int j = 0; j < 8; j++)
        #pragma unroll
        for (int v = 0; v < 4; v++) O[j][v] = 0.f;

    for (int tile = 0; tile < 16; tile++) {
        const int k0 = tile * 64;
        const int buf = tile & 1;
        __syncthreads();   // DM + next-KV buffers free

        // group: dist/mask for this tile
        #pragma unroll
        for (int i = 0; i < 8; i++) {
            const int it = tid + i * 256;          // 0..2047
            const int rr = it >> 4, cc = (it & 15) * 4;
            const size_t go = ((size_t)b * S_ + q0 + rr) * S_ + k0 + cc;
            const uint32_t so = (uint32_t)(rr * DMST + cc) * 4;
            cpa16(sDist + so, dist + go);
            cpa16(sMask + so, maskp + go);
        }
        CP_COMMIT();

        // group: K/V for next tile
        if (tile + 1 < 16) {
            const uint32_t base = sKV0 + (uint32_t)(buf ^ 1) * KV_BUF_B;
            const int nk0 = k0 + 64;
            #pragma unroll
            for (int i = 0; i < 2; i++) {
                const int it = tid + i * 256;
                const int rr = it >> 3, cc = (it & 7) * 8;
                const uint32_t so = (uint32_t)(rr * AST + cc) * 2;
                const size_t go = (size_t)(nk0 + rr) * DK_ + cc;
                cpa16(base + so,                 Kh + go);
                cpa16(base + KV_TILE_B + so,     Kl + go);
                cpa16(base + 2 * KV_TILE_B + so, Vh + go);
                cpa16(base + 3 * KV_TILE_B + so, Vl + go);
            }
        }
        CP_COMMIT();

        CP_WAIT(2);        // current K/V (and Q) resident
        __syncthreads();

        const uint32_t cKh = sKV0 + (uint32_t)buf * KV_BUF_B;
        const uint32_t cKl = cKh + KV_TILE_B;
        const uint32_t cVh = cKh + 2 * KV_TILE_B;
        const uint32_t cVl = cKh + 3 * KV_TILE_B;

        // ---- S = Q K^T ----
        float S[8][4] = {};
        #pragma unroll
        for (int kk = 0; kk < 4; kk++) {
            const uint32_t ao = (uint32_t)((w * 16 + l15) * AST + kk * 16 + (lane >> 4) * 8) * 2;
            uint32_t ah[4], al[4];
            ldsm_x4(ah, sQh + ao);
            ldsm_x4(al, sQl + ao);
            uint32_t bh[4][4], bl[4][4];
            #pragma unroll
            for (int jj = 0; jj < 4; jj++) {
                const uint32_t bo = (uint32_t)((jj * 16 + (g >> 1) * 8 + (lane & 7)) * AST
                                               + kk * 16 + (g & 1) * 8) * 2;
                ldsm_x4(bh[jj], cKh + bo);
                ldsm_x4(bl[jj], cKl + bo);
            }
            #pragma unroll
            for (int jj = 0; jj < 4; jj++) {
                #pragma unroll
                for (int half = 0; half < 2; half++) {
                    const int j = jj * 2 + half;
                    const uint32_t* Bh2 = &bh[jj][half * 2];
                    const uint32_t* Bl2 = &bl[jj][half * 2];
                    mma_bf16(S[j], ah, Bh2);
                    mma_bf16(S[j], al, Bh2);
                    mma_bf16(S[j], ah, Bl2);
                }
            }
        }

        CP_WAIT(1);        // dist/mask resident (next-KV group may still fly)
        __syncthreads();

        // ---- bias * scale, mask, online softmax (dist/mask from smem) ----
        float mx[2];
        mx[0] = mx[1] = -1e30f;
        #pragma unroll
        for (int j = 0; j < 8; j++) {
            #pragma unroll
            for (int c = 0; c < 2; c++) {
                const int qr = w * 16 + r + c * 8;
                const int kc = j * 8 + t * 2;
                const float2 dv = *(const float2*)&fDist[qr * DMST + kc];
                const int2   mv = *(const int2*)&iMask[qr * DMST + kc];

                float bias0 = b2, bias1 = b2;
                #pragma unroll
                for (int hh = 0; hh < 8; hh++) {
                    bias0 += fmaxf(fmaf(dv.x, w1[hh], b1[hh]), 0.f) * w2[hh];
                    bias1 += fmaxf(fmaf(dv.y, w1[hh], b1[hh]), 0.f) * w2[hh];
                }
                float s0 = S[j][c * 2]     * 0.125f * bias0;
                float s1 = S[j][c * 2 + 1] * 0.125f * bias1;
                s0 = (mv.x == 0) ? -1e9f : s0;
                s1 = (mv.y == 0) ? -1e9f : s1;
                S[j][c * 2]     = s0;
                S[j][c * 2 + 1] = s1;
                mx[c] = fmaxf(mx[c], fmaxf(s0, s1));
            }
        }
        #pragma unroll
        for (int c = 0; c < 2; c++) {
            mx[c] = fmaxf(mx[c], __shfl_xor_sync(0xffffffffu, mx[c], 1));
            mx[c] = fmaxf(mx[c], __shfl_xor_sync(0xffffffffu, mx[c], 2));
        }
        float corr[2], rs[2];
        #pragma unroll
        for (int c = 0; c < 2; c++) {
            const float mnew = fmaxf(m_run[c], mx[c]);
            corr[c] = __expf(m_run[c] - mnew);
            m_run[c] = mnew;
            rs[c] = 0.f;
        }
        #pragma unroll
        for (int j = 0; j < 8; j++) {
            #pragma unroll
            for (int c = 0; c < 2; c++) {
                const float p0 = __expf(S[j][c * 2]     - m_run[c]);
                const float p1 = __expf(S[j][c * 2 + 1] - m_run[c]);
                S[j][c * 2]     = p0;
                S[j][c * 2 + 1] = p1;
                rs[c] += p0 + p1;
            }
        }
        #pragma unroll
        for (int c = 0; c < 2; c++) {
            rs[c] += __shfl_xor_sync(0xffffffffu, rs[c], 1);
            rs[c] += __shfl_xor_sync(0xffffffffu, rs[c], 2);
            l_run[c] = l_run[c] * corr[c] + rs[c];
        }
        #pragma unroll
        for (int j = 0; j < 8; j++)
            #pragma unroll
            for (int c = 0; c < 2; c++) {
                O[j][c * 2]     *= corr[c];
                O[j][c * 2 + 1] *= corr[c];
            }

        // ---- pack P fragments ----
        uint32_t pah[4][4], pal[4][4];
        #pragma unroll
        for (int kp = 0; kp < 4; kp++) {
            split2(S[2 * kp][0],     S[2 * kp][1],     pah[kp][0], pal[kp][0]);
            split2(S[2 * kp][2],     S[2 * kp][3],     pah[kp][1], pal[kp][1]);
            split2(S[2 * kp + 1][0], S[2 * kp + 1][1], pah[kp][2], pal[kp][2]);
            split2(S[2 * kp + 1][2], S[2 * kp + 1][3], pah[kp][3], pal[kp][3]);
        }

        // ---- O += P @ V ----
        #pragma unroll
        for (int kp = 0; kp < 4; kp++) {
            #pragma unroll
            for (int dj2 = 0; dj2 < 4; dj2++) {
                const uint32_t vo = (uint32_t)((kp * 16 + l15) * AST
                                               + dj2 * 16 + ((lane >> 4) & 1) * 8) * 2;
                uint32_t bh[4], bl[4];
                ldsm_x4t(bh, cVh + vo);
                ldsm_x4t(bl, cVl + vo);
                #pragma unroll
                for (int half = 0; half < 2; half++) {
                    const int dj = dj2 * 2 + half;
                    const uint32_t* Bh2 = &bh[half * 2];
                    const uint32_t* Bl2 = &bl[half * 2];
                    mma_bf16(O[dj], pah[kp], Bh2);
                    mma_bf16(O[dj], pal[kp], Bh2);
                    mma_bf16(O[dj], pah[kp], Bl2);
                }
            }
        }
    }

    // ---- normalize + split-store ----
    const float inv0 = 1.0f / l_run[0];
    const float inv1 = 1.0f / l_run[1];
    #pragma unroll
    for (int dj = 0; dj < 8; dj++) {
        #pragma unroll
        for (int c = 0; c < 2; c++) {
            const int qg = q0 + w * 16 + r + c * 8;
            const int d = dj * 8 + t * 2;
            const float inv = c ? inv1 : inv0;
            uint32_t hi, lo;
            split2(O[dj][c * 2] * inv, O[dj][c * 2 + 1] * inv, hi, lo);
            const size_t o = ((size_t)b * S_ + qg) * E_ + h * 64 + d;
            *(uint32_t*)&x_h[o] = hi;
            *(uint32_t*)&x_l[o] = lo;
        }
    }
}

// ---------------------------------------------------------------------------
// Launch
// ---------------------------------------------------------------------------
extern "C" void kernel_launch(void* const* d_in, const int* in_sizes, int n_in,
                              void* d_out, int out_size)
{
    (void)in_sizes; (void)n_in; (void)out_size;
    const float* query = (const float*)d_in[0];
    const float* key   = (const float*)d_in[1];
    const float* value = (const float*)d_in[2];
    const float* dist  = (const float*)d_in[3];
    const int*   maskp = (const int*)  d_in[4];
    const float* Wq = (const float*)d_in[5];
    const float* bq = (const float*)d_in[6];
    const float* Wk = (const float*)d_in[7];
    const float* bk = (const float*)d_in[8];
    const float* Wv = (const float*)d_in[9];
    const float* bv = (const float*)d_in[10];
    const float* Wo = (const float*)d_in[11];
    const float* bo = (const float*)d_in[12];
    const float* cw1 = (const float*)d_in[13];
    const float* cb1 = (const float*)d_in[14];
    const float* cw2 = (const float*)d_in[15];
    const float* cb2 = (const float*)d_in[16];
    float* out = (float*)d_out;

    cudaFuncSetAttribute(gemm_qkv_kernel, cudaFuncAttributeMaxDynamicSharedMemorySize, GEMM_SMEM_BYTES);
    cudaFuncSetAttribute(gemm_out_kernel, cudaFuncAttributeMaxDynamicSharedMemorySize, GEMM_SMEM_BYTES);
    cudaFuncSetAttribute(attn_kernel,     cudaFuncAttributeMaxDynamicSharedMemorySize, ATTN_SMEM_BYTES);

    conv7_kernel<<<dim3(2048, 1, 7), 256>>>(query, key, value, Wq, Wk, Wv, Wo);

    gemm_qkv_kernel<<<dim3(M_ / 128, E_ / 128, 3), 256, GEMM_SMEM_BYTES>>>(bq, bk, bv);

    attn_kernel<<<dim3(B_ * H_, S_ / 128), 256, ATTN_SMEM_BYTES>>>(
        dist, maskp, cw1, cb1, cw2, cb2);

    gemm_out_kernel<<<dim3(M_ / 128, E_ / 128), 256, GEMM_SMEM_BYTES>>>(bo, out);
}